// round 15
// baseline (speedup 1.0000x reference)
#include <cuda_runtime.h>
#include <cuda_bf16.h>
#include <cstdint>
#include <math.h>

#define B_ 8
#define T_ 2048
#define C_ 512
#define H_ 64
#define NQT128 (T_ / 128)     // 16 q-tiles of 128 rows

// ---- device scratch (no allocations allowed) ----
__device__ __align__(16) __nv_bfloat16 g_whi[3][H_][C_];
__device__ __align__(16) __nv_bfloat16 g_wlo[3][H_][C_];
__device__ __align__(16) __nv_bfloat16 g_qhi[B_ * T_][H_];
__device__ __align__(16) __nv_bfloat16 g_qlo[B_ * T_][H_];
__device__ __align__(16) __nv_bfloat16 g_khi[B_ * T_][H_];
__device__ __align__(16) __nv_bfloat16 g_klo[B_ * T_][H_];
__device__ __align__(16) __nv_bfloat16 g_vthi[H_][B_ * T_];
__device__ __align__(16) __nv_bfloat16 g_vtlo[H_][B_ * T_];
__device__ __align__(16) float g_pm[2][B_][T_];
__device__ __align__(16) float g_pl[2][B_][T_];
__device__ __align__(16) float g_po[2][B_][T_][H_];

// ---- helpers ----
__device__ __forceinline__ void mma_bf16(float* d, const uint32_t* a, uint32_t b0,
                                         uint32_t b1) {
    asm volatile(
        "mma.sync.aligned.m16n8k16.row.col.f32.bf16.bf16.f32 "
        "{%0,%1,%2,%3}, {%4,%5,%6,%7}, {%8,%9}, {%0,%1,%2,%3};"
        : "+f"(d[0]), "+f"(d[1]), "+f"(d[2]), "+f"(d[3])
        : "r"(a[0]), "r"(a[1]), "r"(a[2]), "r"(a[3]), "r"(b0), "r"(b1));
}
__device__ __forceinline__ uint32_t packbf2(float a, float b) {
    __nv_bfloat162 t = __floats2bfloat162_rn(a, b);
    return *(uint32_t*)&t;
}
__device__ __forceinline__ uint32_t smem_u32(const void* p) {
    uint32_t a;
    asm("{ .reg .u64 t; cvta.to.shared.u64 t, %1; cvt.u32.u64 %0, t; }" : "=r"(a) : "l"(p));
    return a;
}
__device__ __forceinline__ void cp_async16(uint32_t dst, const void* src) {
    asm volatile("cp.async.cg.shared.global [%0], [%1], 16;" :: "r"(dst), "l"(src));
}
__device__ __forceinline__ void cp_commit() {
    asm volatile("cp.async.commit_group;" ::: "memory");
}
__device__ __forceinline__ void cp_wait0() {
    asm volatile("cp.async.wait_group 0;" ::: "memory");
}
__device__ __forceinline__ void cp_wait1() {
    asm volatile("cp.async.wait_group 1;" ::: "memory");
}

// ---------------------------------------------------------------------------
// prep_w v2 (R14): coalesced reads, scattered (latency-insensitive) writes.
// ---------------------------------------------------------------------------
__global__ void prep_w_kernel(const float* __restrict__ Wq,
                              const float* __restrict__ Wk,
                              const float* __restrict__ Wv) {
    int idx = blockIdx.x * 256 + threadIdx.x;
    int o = idx >> 15;
    int k = (idx >> 6) & 511;
    int n = idx & 63;
    const float* W = (o == 0) ? Wq : ((o == 1) ? Wk : Wv);
    float v = W[(size_t)k * H_ + n];
    __nv_bfloat16 hi = __float2bfloat16(v);
    __nv_bfloat16 lo = __float2bfloat16(v - __bfloat162float(hi));
    g_whi[o][n][k] = hi;
    g_wlo[o][n][k] = lo;
}

// ---------------------------------------------------------------------------
// Projection v7 (R14): chunk pipeline, cp.async B double-buffer, x prefetch.
// grid = 128, block = 256 (8 warps), dynamic smem = 147456 B
// ---------------------------------------------------------------------------
#define AP 72
#define SM_AHI 0
#define SM_ALO (128 * AP * 2)          // 18432
#define SM_B   (2 * 128 * AP * 2)      // 36864
#define BT_SZ  (64 * AP * 2)           // 9216
#define BBUF   (6 * BT_SZ)             // 55296
#define PROJ_SMEM (SM_B + 2 * BBUF)    // 147456
#define VSP 136

__device__ __forceinline__ void proj_issue_b(uint32_t sbB, int c, int tid) {
    #pragma unroll
    for (int j = 0; j < 12; j++) {
        int i = tid + j * 256;
        int t = i >> 9, rem = i & 511;
        int n = rem >> 3, q8 = rem & 7;
        int o = (t >= 3) ? (t - 3) : t;
        const __nv_bfloat16* src = (t >= 3) ? &g_wlo[o][n][c * 64 + q8 * 8]
                                            : &g_whi[o][n][c * 64 + q8 * 8];
        cp_async16(sbB + (uint32_t)(t * BT_SZ + (n * AP + q8 * 8) * 2), src);
    }
    cp_commit();
}
__device__ __forceinline__ void proj_load_x(const float* __restrict__ x,
                                            int rowBase, int c, int tid, float4* xv) {
    #pragma unroll
    for (int j = 0; j < 8; j++) {
        int i = tid + j * 256;
        int r = i >> 4, q4 = i & 15;
        xv[j] = *(const float4*)&x[(size_t)(rowBase + r) * C_ + c * 64 + q4 * 4];
    }
}

__global__ void __launch_bounds__(256, 1) proj_kernel(const float* __restrict__ x) {
    extern __shared__ __align__(16) char smem[];
    const uint32_t sbase = smem_u32(smem);
    const int tid = threadIdx.x;
    const int wid = tid >> 5;
    const int lane = tid & 31;
    const int g = lane >> 2;
    const int tq = lane & 3;
    const int rowBase = blockIdx.x * 128;

    float d[3][8][4];
    #pragma unroll
    for (int o = 0; o < 3; o++)
        #pragma unroll
        for (int nt = 0; nt < 8; nt++)
            #pragma unroll
            for (int r = 0; r < 4; r++) d[o][nt][r] = 0.0f;

    float4 xv[8];
    proj_issue_b(sbase + SM_B, 0, tid);
    proj_load_x(x, rowBase, 0, tid, xv);

    for (int c = 0; c < 8; c++) {
        __syncthreads();   // A-buffer WAR vs mma(c-1)
        #pragma unroll
        for (int j = 0; j < 8; j++) {
            int i = tid + j * 256;
            int r = i >> 4, q4 = i & 15;
            float4 v = xv[j];
            __nv_bfloat16 h0 = __float2bfloat16(v.x), h1 = __float2bfloat16(v.y);
            __nv_bfloat16 h2 = __float2bfloat16(v.z), h3 = __float2bfloat16(v.w);
            float l0 = v.x - __bfloat162float(h0), l1 = v.y - __bfloat162float(h1);
            float l2 = v.z - __bfloat162float(h2), l3 = v.w - __bfloat162float(h3);
            uint32_t off = (uint32_t)(r * AP + q4 * 4) * 2;
            __nv_bfloat162 hA; hA.x = h0; hA.y = h1;
            __nv_bfloat162 hB; hB.x = h2; hB.y = h3;
            *(uint2*)(smem + SM_AHI + off) = make_uint2(*(uint32_t*)&hA, *(uint32_t*)&hB);
            *(uint2*)(smem + SM_ALO + off) = make_uint2(packbf2(l0, l1), packbf2(l2, l3));
        }
        if (c < 7) {
            proj_load_x(x, rowBase, c + 1, tid, xv);
            proj_issue_b(sbase + SM_B + ((c + 1) & 1) * BBUF, c + 1, tid);
            cp_wait1();
        } else {
            cp_wait0();
        }
        __syncthreads();

        uint32_t aHi[4][4], aLo[4][4];
        {
            const int r0 = wid * 16 + g;
            #pragma unroll
            for (int ks = 0; ks < 4; ks++) {
                const int k0 = ks * 16 + tq * 2;
                uint32_t o00 = (uint32_t)(r0 * AP + k0) * 2;
                uint32_t o10 = (uint32_t)((r0 + 8) * AP + k0) * 2;
                aHi[ks][0] = *(const uint32_t*)(smem + SM_AHI + o00);
                aHi[ks][1] = *(const uint32_t*)(smem + SM_AHI + o10);
                aHi[ks][2] = *(const uint32_t*)(smem + SM_AHI + o00 + 16);
                aHi[ks][3] = *(const uint32_t*)(smem + SM_AHI + o10 + 16);
                aLo[ks][0] = *(const uint32_t*)(smem + SM_ALO + o00);
                aLo[ks][1] = *(const uint32_t*)(smem + SM_ALO + o10);
                aLo[ks][2] = *(const uint32_t*)(smem + SM_ALO + o00 + 16);
                aLo[ks][3] = *(const uint32_t*)(smem + SM_ALO + o10 + 16);
            }
        }

        const char* bbase = smem + SM_B + (c & 1) * BBUF;
        #pragma unroll
        for (int o = 0; o < 3; o++) {
            const char* bHi = bbase + o * BT_SZ;
            const char* bLo = bbase + (o + 3) * BT_SZ;
            #pragma unroll
            for (int ks = 0; ks < 4; ks++) {
                const int k0 = ks * 16 + tq * 2;
                uint32_t bf[8][2];
                #pragma unroll
                for (int nt = 0; nt < 8; nt++) {
                    uint32_t ob = (uint32_t)((nt * 8 + g) * AP + k0) * 2;
                    bf[nt][0] = *(const uint32_t*)(bHi + ob);
                    bf[nt][1] = *(const uint32_t*)(bHi + ob + 16);
                }
                #pragma unroll
                for (int nt = 0; nt < 8; nt++) {
                    mma_bf16(d[o][nt], aHi[ks], bf[nt][0], bf[nt][1]);
                    mma_bf16(d[o][nt], aLo[ks], bf[nt][0], bf[nt][1]);
                }
                #pragma unroll
                for (int nt = 0; nt < 8; nt++) {
                    uint32_t ob = (uint32_t)((nt * 8 + g) * AP + k0) * 2;
                    bf[nt][0] = *(const uint32_t*)(bLo + ob);
                    bf[nt][1] = *(const uint32_t*)(bLo + ob + 16);
                }
                #pragma unroll
                for (int nt = 0; nt < 8; nt++)
                    mma_bf16(d[o][nt], aHi[ks], bf[nt][0], bf[nt][1]);
            }
        }
    }
    __syncthreads();

    const size_t r0 = (size_t)(rowBase + wid * 16 + g);
    #pragma unroll
    for (int o = 0; o < 2; o++) {
        __nv_bfloat16 (*dsthi)[H_] = o ? g_khi : g_qhi;
        __nv_bfloat16 (*dstlo)[H_] = o ? g_klo : g_qlo;
        #pragma unroll
        for (int nt = 0; nt < 8; nt++) {
            int col = nt * 8 + tq * 2;
            #pragma unroll
            for (int h = 0; h < 2; h++) {
                float v0 = d[o][nt][h * 2], v1 = d[o][nt][h * 2 + 1];
                __nv_bfloat16 h0 = __float2bfloat16(v0), h1 = __float2bfloat16(v1);
                float l0 = v0 - __bfloat162float(h0), l1 = v1 - __bfloat162float(h1);
                __nv_bfloat162 hp; hp.x = h0; hp.y = h1;
                *(uint32_t*)&dsthi[r0 + h * 8][col] = *(uint32_t*)&hp;
                *(uint32_t*)&dstlo[r0 + h * 8][col] = packbf2(l0, l1);
            }
        }
    }
    {
        __nv_bfloat16 (*sVhi)[VSP] = (__nv_bfloat16(*)[VSP])(smem + SM_B);
        __nv_bfloat16 (*sVlo)[VSP] =
            (__nv_bfloat16(*)[VSP])(smem + SM_B + 64 * VSP * 2);
        int tl0 = wid * 16 + g;
        #pragma unroll
        for (int nt = 0; nt < 8; nt++) {
            #pragma unroll
            for (int j = 0; j < 4; j++) {
                int col = nt * 8 + tq * 2 + (j & 1);
                int tl = tl0 + (j >> 1) * 8;
                float v = d[2][nt][j];
                __nv_bfloat16 hi = __float2bfloat16(v);
                sVhi[col][tl] = hi;
                sVlo[col][tl] = __float2bfloat16(v - __bfloat162float(hi));
            }
        }
        __syncthreads();
        for (int i = tid; i < 64 * 16; i += 256) {
            int h = i >> 4, q8 = i & 15;
            *(uint4*)&g_vthi[h][rowBase + q8 * 8] = *(const uint4*)&sVhi[h][q8 * 8];
            *(uint4*)&g_vtlo[h][rowBase + q8 * 8] = *(const uint4*)&sVlo[h][q8 * 8];
        }
    }
}

// ---------------------------------------------------------------------------
// Flash attention v5: ONE q-tile per block (side loop removed), grid
// (16,2,8) = 256 blocks, __launch_bounds__(256,2) -> occ 2/SM -> 4 warps
// per SMSP (vs 2) to hide mma/LDS/expf dependency chains. All 256 blocks
// fit in 296 residency slots, so the triangular imbalance resolves by
// co-scheduling. Per-(qt,b,hf) math identical to R14 -> rel_err unchanged.
// smem: 2 x 36864 + sP 18432 = 92160 (x2 blocks = 184KB <= 228KB).
// ---------------------------------------------------------------------------
#define APB 72
#define ROWB (APB * 2)
#define TILE_SZ 36864
#define SK_HI 0
#define SK_LO 9216
#define SV_HI 18432
#define SV_LO 27648
#define SP_OFF (2 * TILE_SZ)
#define ATTN_SMEM (SP_OFF + 128 * ROWB)   // 92160

__device__ __forceinline__ void attn_issue_tile(uint32_t sb, int b, int kt, int tid) {
    #pragma unroll
    for (int j = 0; j < 8; j++) {
        int i = tid + j * 256;
        int which = i >> 9, rem = i & 511;
        int r = rem >> 3, q8 = rem & 7;
        const __nv_bfloat16* src;
        if      (which == 0) src = &g_khi[(size_t)b * T_ + kt * 64 + r][q8 * 8];
        else if (which == 1) src = &g_klo[(size_t)b * T_ + kt * 64 + r][q8 * 8];
        else if (which == 2) src = &g_vthi[r][(size_t)b * T_ + kt * 64 + q8 * 8];
        else                 src = &g_vtlo[r][(size_t)b * T_ + kt * 64 + q8 * 8];
        cp_async16(sb + which * 9216 + r * ROWB + q8 * 16, src);
    }
    cp_commit();
}

__global__ void __launch_bounds__(256, 2) attn_kernel() {
    extern __shared__ __align__(16) char sm[];
    const uint32_t sbase = smem_u32(sm);
    const int qt   = blockIdx.x;     // 0..15
    const int hf   = blockIdx.y;
    const int b    = blockIdx.z;
    const int tid  = threadIdx.x;
    const int wid  = tid >> 5;
    const int lane = tid & 31;
    const int g    = lane >> 2;
    const int tq   = lane & 3;

    const int row0 = qt * 128 + wid * 16 + g;
    const int row1 = row0 + 8;
    const size_t tok0 = (size_t)b * T_ + row0;

    uint32_t qhi[4][4], qlo[4][4];
    #pragma unroll
    for (int ks = 0; ks < 4; ks++) {
        const int k0 = ks * 16 + tq * 2;
        qhi[ks][0] = *(const uint32_t*)&g_qhi[tok0][k0];
        qhi[ks][1] = *(const uint32_t*)&g_qhi[tok0 + 8][k0];
        qhi[ks][2] = *(const uint32_t*)&g_qhi[tok0][k0 + 8];
        qhi[ks][3] = *(const uint32_t*)&g_qhi[tok0 + 8][k0 + 8];
        qlo[ks][0] = *(const uint32_t*)&g_qlo[tok0][k0];
        qlo[ks][1] = *(const uint32_t*)&g_qlo[tok0 + 8][k0];
        qlo[ks][2] = *(const uint32_t*)&g_qlo[tok0][k0 + 8];
        qlo[ks][3] = *(const uint32_t*)&g_qlo[tok0 + 8][k0 + 8];
    }

    float O[8][4];
    #pragma unroll
    for (int nt = 0; nt < 8; nt++)
        #pragma unroll
        for (int r = 0; r < 4; r++) O[nt][r] = 0.0f;
    float m0 = -1e30f, m1 = -1e30f, l0 = 0.0f, l1 = 0.0f;

    const int kt0 = hf ? (qt + 1)     : 0;
    const int kt1 = hf ? (2 * qt + 2) : (qt + 1);
    const int ntl = kt1 - kt0;

    attn_issue_tile(sbase, b, kt0, tid);

    for (int it = 0; it < ntl; it++) {
        const int kt = kt0 + it;
        const char* buf = sm + (it & 1) * TILE_SZ;
        cp_wait0();
        __syncthreads();
        if (it + 1 < ntl)
            attn_issue_tile(sbase + ((it + 1) & 1) * TILE_SZ, b, kt + 1, tid);

        float s[8][4];
        #pragma unroll
        for (int nt = 0; nt < 8; nt++)
            #pragma unroll
            for (int r = 0; r < 4; r++) s[nt][r] = 0.0f;
        #pragma unroll
        for (int ks = 0; ks < 4; ks++) {
            const int kb = (ks * 16 + tq * 2) * 2;
            #pragma unroll
            for (int nt = 0; nt < 8; nt++) {
                const char* rh = buf + SK_HI + (nt * 8 + g) * ROWB;
                uint32_t b0 = *(const uint32_t*)(rh + kb);
                uint32_t b1 = *(const uint32_t*)(rh + kb + 16);
                mma_bf16(s[nt], qhi[ks], b0, b1);
                mma_bf16(s[nt], qlo[ks], b0, b1);
                const char* rl = buf + SK_LO + (nt * 8 + g) * ROWB;
                uint32_t c0 = *(const uint32_t*)(rl + kb);
                uint32_t c1 = *(const uint32_t*)(rl + kb + 16);
                mma_bf16(s[nt], qhi[ks], c0, c1);
            }
        }

        if (kt >= 2 * qt) {
            #pragma unroll
            for (int nt = 0; nt < 8; nt++) {
                int col = kt * 64 + nt * 8 + tq * 2;
                if (col > row0)     s[nt][0] = -1e30f;
                if (col + 1 > row0) s[nt][1] = -1e30f;
                if (col > row1)     s[nt][2] = -1e30f;
                if (col + 1 > row1) s[nt][3] = -1e30f;
            }
        }

        float a0 = -1e30f, a1 = -1e30f;
        #pragma unroll
        for (int nt = 0; nt < 8; nt++) {
            a0 = fmaxf(a0, fmaxf(s[nt][0], s[nt][1]));
            a1 = fmaxf(a1, fmaxf(s[nt][2], s[nt][3]));
        }
        a0 = fmaxf(a0, __shfl_xor_sync(0xffffffffu, a0, 1));
        a0 = fmaxf(a0, __shfl_xor_sync(0xffffffffu, a0, 2));
        a1 = fmaxf(a1, __shfl_xor_sync(0xffffffffu, a1, 1));
        a1 = fmaxf(a1, __shfl_xor_sync(0xffffffffu, a1, 2));
        float nm0 = fmaxf(m0, a0), nm1 = fmaxf(m1, a1);
        float sc0 = __expf(m0 - nm0), sc1 = __expf(m1 - nm1);
        float rs0 = 0.0f, rs1 = 0.0f;
        char* prow0 = sm + SP_OFF + (wid * 16 + g) * ROWB;
        #pragma unroll
        for (int nt = 0; nt < 8; nt++) {
            float p00 = __expf(s[nt][0] - nm0), p01 = __expf(s[nt][1] - nm0);
            float p10 = __expf(s[nt][2] - nm1), p11 = __expf(s[nt][3] - nm1);
            __nv_bfloat162 r0p = __floats2bfloat162_rn(p00, p01);
            __nv_bfloat162 r1p = __floats2bfloat162_rn(p10, p11);
            rs0 += __bfloat162float(r0p.x) + __bfloat162float(r0p.y);
            rs1 += __bfloat162float(r1p.x) + __bfloat162float(r1p.y);
            *(uint32_t*)(prow0 + (nt * 8 + tq * 2) * 2) = *(uint32_t*)&r0p;
            *(uint32_t*)(prow0 + 8 * ROWB + (nt * 8 + tq * 2) * 2) = *(uint32_t*)&r1p;
        }
        rs0 += __shfl_xor_sync(0xffffffffu, rs0, 1);
        rs0 += __shfl_xor_sync(0xffffffffu, rs0, 2);
        rs1 += __shfl_xor_sync(0xffffffffu, rs1, 1);
        rs1 += __shfl_xor_sync(0xffffffffu, rs1, 2);
        l0 = l0 * sc0 + rs0; m0 = nm0;
        l1 = l1 * sc1 + rs1; m1 = nm1;
        #pragma unroll
        for (int nt = 0; nt < 8; nt++) {
            O[nt][0] *= sc0; O[nt][1] *= sc0;
            O[nt][2] *= sc1; O[nt][3] *= sc1;
        }
        __syncwarp();

        #pragma unroll
        for (int ks = 0; ks < 4; ks++) {
            const int kb = (ks * 16 + tq * 2) * 2;
            uint32_t pa[4];
            const char* pr = sm + SP_OFF + (wid * 16 + g) * ROWB;
            pa[0] = *(const uint32_t*)(pr + kb);
            pa[1] = *(const uint32_t*)(pr + 8 * ROWB + kb);
            pa[2] = *(const uint32_t*)(pr + kb + 16);
            pa[3] = *(const uint32_t*)(pr + 8 * ROWB + kb + 16);
            #pragma unroll
            for (int nt = 0; nt < 8; nt++) {
                const char* vh = buf + SV_HI + (nt * 8 + g) * ROWB;
                uint32_t b0 = *(const uint32_t*)(vh + kb);
                uint32_t b1 = *(const uint32_t*)(vh + kb + 16);
                mma_bf16(O[nt], pa, b0, b1);
                const char* vl = buf + SV_LO + (nt * 8 + g) * ROWB;
                b0 = *(const uint32_t*)(vl + kb);
                b1 = *(const uint32_t*)(vl + kb + 16);
                mma_bf16(O[nt], pa, b0, b1);
            }
        }
    }

    if (tq == 0) {
        g_pm[hf][b][row0] = m0; g_pl[hf][b][row0] = l0;
        g_pm[hf][b][row1] = m1; g_pl[hf][b][row1] = l1;
    }
    #pragma unroll
    for (int nt = 0; nt < 8; nt++) {
        int col = nt * 8 + tq * 2;
        *(float2*)&g_po[hf][b][row0][col] = make_float2(O[nt][0], O[nt][1]);
        *(float2*)&g_po[hf][b][row1][col] = make_float2(O[nt][2], O[nt][3]);
    }
}

// ---------------------------------------------------------------------------
// Merge split-K halves.
// ---------------------------------------------------------------------------
__global__ void merge_kernel(float* __restrict__ out) {
    int idx = blockIdx.x * 256 + threadIdx.x;
    int row = idx >> 4;
    int c4  = idx & 15;
    int b = row >> 11;
    int t = row & 2047;

    float m0 = g_pm[0][b][t], m1 = g_pm[1][b][t];
    float l0 = g_pl[0][b][t], l1 = g_pl[1][b][t];
    float M  = fmaxf(m0, m1);
    float e0 = __expf(m0 - M), e1 = __expf(m1 - M);
    float inv = 1.0f / (l0 * e0 + l1 * e1);

    float4 a0 = *(const float4*)&g_po[0][b][t][c4 * 4];
    float4 a1 = *(const float4*)&g_po[1][b][t][c4 * 4];
    float4 o;
    o.x = (a0.x * e0 + a1.x * e1) * inv;
    o.y = (a0.y * e0 + a1.y * e1) * inv;
    o.z = (a0.z * e0 + a1.z * e1) * inv;
    o.w = (a0.w * e0 + a1.w * e1) * inv;
    *(float4*)&out[(size_t)row * H_ + c4 * 4] = o;
}

// ---------------------------------------------------------------------------
// Harness entry. Inputs: x [B,T,C], Wq, Wk, Wv [C,H]. Output: [B,T,H] f32.
// ---------------------------------------------------------------------------
extern "C" void kernel_launch(void* const* d_in, const int* in_sizes, int n_in,
                              void* d_out, int out_size) {
    const float* x  = (const float*)d_in[0];
    const float* Wq = (const float*)d_in[1];
    const float* Wk = (const float*)d_in[2];
    const float* Wv = (const float*)d_in[3];
    float* out = (float*)d_out;
    (void)in_sizes; (void)n_in; (void)out_size;

    cudaFuncSetAttribute(proj_kernel, cudaFuncAttributeMaxDynamicSharedMemorySize,
                         PROJ_SMEM);
    cudaFuncSetAttribute(attn_kernel, cudaFuncAttributeMaxDynamicSharedMemorySize,
                         ATTN_SMEM);

    prep_w_kernel<<<384, 256>>>(Wq, Wk, Wv);
    proj_kernel<<<128, 256, PROJ_SMEM>>>(x);
    attn_kernel<<<dim3(NQT128, 2, B_), 256, ATTN_SMEM>>>();
    merge_kernel<<<(B_ * T_ * (H_ / 4)) / 256, 256>>>(out);
}

// round 16
// speedup vs baseline: 1.4000x; 1.4000x over previous
#include <cuda_runtime.h>
#include <cuda_bf16.h>
#include <cstdint>
#include <math.h>

#define B_ 8
#define T_ 2048
#define C_ 512
#define H_ 64
#define NQT128 (T_ / 128)     // 16 q-tiles of 128 rows
#define NPAIR (NQT128 / 2)    // 8 balanced pairs

// ---- device scratch (no allocations allowed) ----
__device__ __align__(16) __nv_bfloat16 g_whi[3][H_][C_];
__device__ __align__(16) __nv_bfloat16 g_wlo[3][H_][C_];
__device__ __align__(16) __nv_bfloat16 g_qhi[B_ * T_][H_];
__device__ __align__(16) __nv_bfloat16 g_qlo[B_ * T_][H_];
__device__ __align__(16) __nv_bfloat16 g_khi[B_ * T_][H_];
__device__ __align__(16) __nv_bfloat16 g_klo[B_ * T_][H_];
__device__ __align__(16) __nv_bfloat16 g_vthi[H_][B_ * T_];
__device__ __align__(16) __nv_bfloat16 g_vtlo[H_][B_ * T_];
__device__ __align__(16) float g_pm[2][B_][T_];
__device__ __align__(16) float g_pl[2][B_][T_];
__device__ __align__(16) float g_po[2][B_][T_][H_];

// ---- helpers ----
__device__ __forceinline__ void mma_bf16(float* d, const uint32_t* a, uint32_t b0,
                                         uint32_t b1) {
    asm volatile(
        "mma.sync.aligned.m16n8k16.row.col.f32.bf16.bf16.f32 "
        "{%0,%1,%2,%3}, {%4,%5,%6,%7}, {%8,%9}, {%0,%1,%2,%3};"
        : "+f"(d[0]), "+f"(d[1]), "+f"(d[2]), "+f"(d[3])
        : "r"(a[0]), "r"(a[1]), "r"(a[2]), "r"(a[3]), "r"(b0), "r"(b1));
}
__device__ __forceinline__ void ldsm_x4(uint32_t& r0, uint32_t& r1, uint32_t& r2,
                                        uint32_t& r3, uint32_t addr) {
    asm volatile("ldmatrix.sync.aligned.m8n8.x4.shared.b16 {%0,%1,%2,%3}, [%4];"
                 : "=r"(r0), "=r"(r1), "=r"(r2), "=r"(r3) : "r"(addr));
}
__device__ __forceinline__ uint32_t packbf2(float a, float b) {
    __nv_bfloat162 t = __floats2bfloat162_rn(a, b);
    return *(uint32_t*)&t;
}
__device__ __forceinline__ uint32_t smem_u32(const void* p) {
    uint32_t a;
    asm("{ .reg .u64 t; cvta.to.shared.u64 t, %1; cvt.u32.u64 %0, t; }" : "=r"(a) : "l"(p));
    return a;
}
__device__ __forceinline__ void cp_async16(uint32_t dst, const void* src) {
    asm volatile("cp.async.cg.shared.global [%0], [%1], 16;" :: "r"(dst), "l"(src));
}
__device__ __forceinline__ void cp_commit() {
    asm volatile("cp.async.commit_group;" ::: "memory");
}
__device__ __forceinline__ void cp_wait0() {
    asm volatile("cp.async.wait_group 0;" ::: "memory");
}
__device__ __forceinline__ void cp_wait1() {
    asm volatile("cp.async.wait_group 1;" ::: "memory");
}

// ---------------------------------------------------------------------------
// prep_w v2 (R14): coalesced reads.
// ---------------------------------------------------------------------------
__global__ void prep_w_kernel(const float* __restrict__ Wq,
                              const float* __restrict__ Wk,
                              const float* __restrict__ Wv) {
    int idx = blockIdx.x * 256 + threadIdx.x;
    int o = idx >> 15;
    int k = (idx >> 6) & 511;
    int n = idx & 63;
    const float* W = (o == 0) ? Wq : ((o == 1) ? Wk : Wv);
    float v = W[(size_t)k * H_ + n];
    __nv_bfloat16 hi = __float2bfloat16(v);
    __nv_bfloat16 lo = __float2bfloat16(v - __bfloat162float(hi));
    g_whi[o][n][k] = hi;
    g_wlo[o][n][k] = lo;
}

// ---------------------------------------------------------------------------
// Projection v7 (R14, unchanged): chunk pipeline.
// ---------------------------------------------------------------------------
#define AP 72
#define SM_AHI 0
#define SM_ALO (128 * AP * 2)
#define SM_B   (2 * 128 * AP * 2)
#define BT_SZ  (64 * AP * 2)
#define BBUF   (6 * BT_SZ)
#define PROJ_SMEM (SM_B + 2 * BBUF)
#define VSP 136

__device__ __forceinline__ void proj_issue_b(uint32_t sbB, int c, int tid) {
    #pragma unroll
    for (int j = 0; j < 12; j++) {
        int i = tid + j * 256;
        int t = i >> 9, rem = i & 511;
        int n = rem >> 3, q8 = rem & 7;
        int o = (t >= 3) ? (t - 3) : t;
        const __nv_bfloat16* src = (t >= 3) ? &g_wlo[o][n][c * 64 + q8 * 8]
                                            : &g_whi[o][n][c * 64 + q8 * 8];
        cp_async16(sbB + (uint32_t)(t * BT_SZ + (n * AP + q8 * 8) * 2), src);
    }
    cp_commit();
}
__device__ __forceinline__ void proj_load_x(const float* __restrict__ x,
                                            int rowBase, int c, int tid, float4* xv) {
    #pragma unroll
    for (int j = 0; j < 8; j++) {
        int i = tid + j * 256;
        int r = i >> 4, q4 = i & 15;
        xv[j] = *(const float4*)&x[(size_t)(rowBase + r) * C_ + c * 64 + q4 * 4];
    }
}

__global__ void __launch_bounds__(256, 1) proj_kernel(const float* __restrict__ x) {
    extern __shared__ __align__(16) char smem[];
    const uint32_t sbase = smem_u32(smem);
    const int tid = threadIdx.x;
    const int wid = tid >> 5;
    const int lane = tid & 31;
    const int g = lane >> 2;
    const int tq = lane & 3;
    const int rowBase = blockIdx.x * 128;

    float d[3][8][4];
    #pragma unroll
    for (int o = 0; o < 3; o++)
        #pragma unroll
        for (int nt = 0; nt < 8; nt++)
            #pragma unroll
            for (int r = 0; r < 4; r++) d[o][nt][r] = 0.0f;

    float4 xv[8];
    proj_issue_b(sbase + SM_B, 0, tid);
    proj_load_x(x, rowBase, 0, tid, xv);

    for (int c = 0; c < 8; c++) {
        __syncthreads();
        #pragma unroll
        for (int j = 0; j < 8; j++) {
            int i = tid + j * 256;
            int r = i >> 4, q4 = i & 15;
            float4 v = xv[j];
            __nv_bfloat16 h0 = __float2bfloat16(v.x), h1 = __float2bfloat16(v.y);
            __nv_bfloat16 h2 = __float2bfloat16(v.z), h3 = __float2bfloat16(v.w);
            float l0 = v.x - __bfloat162float(h0), l1 = v.y - __bfloat162float(h1);
            float l2 = v.z - __bfloat162float(h2), l3 = v.w - __bfloat162float(h3);
            uint32_t off = (uint32_t)(r * AP + q4 * 4) * 2;
            __nv_bfloat162 hA; hA.x = h0; hA.y = h1;
            __nv_bfloat162 hB; hB.x = h2; hB.y = h3;
            *(uint2*)(smem + SM_AHI + off) = make_uint2(*(uint32_t*)&hA, *(uint32_t*)&hB);
            *(uint2*)(smem + SM_ALO + off) = make_uint2(packbf2(l0, l1), packbf2(l2, l3));
        }
        if (c < 7) {
            proj_load_x(x, rowBase, c + 1, tid, xv);
            proj_issue_b(sbase + SM_B + ((c + 1) & 1) * BBUF, c + 1, tid);
            cp_wait1();
        } else {
            cp_wait0();
        }
        __syncthreads();

        uint32_t aHi[4][4], aLo[4][4];
        {
            const int r0 = wid * 16 + g;
            #pragma unroll
            for (int ks = 0; ks < 4; ks++) {
                const int k0 = ks * 16 + tq * 2;
                uint32_t o00 = (uint32_t)(r0 * AP + k0) * 2;
                uint32_t o10 = (uint32_t)((r0 + 8) * AP + k0) * 2;
                aHi[ks][0] = *(const uint32_t*)(smem + SM_AHI + o00);
                aHi[ks][1] = *(const uint32_t*)(smem + SM_AHI + o10);
                aHi[ks][2] = *(const uint32_t*)(smem + SM_AHI + o00 + 16);
                aHi[ks][3] = *(const uint32_t*)(smem + SM_AHI + o10 + 16);
                aLo[ks][0] = *(const uint32_t*)(smem + SM_ALO + o00);
                aLo[ks][1] = *(const uint32_t*)(smem + SM_ALO + o10);
                aLo[ks][2] = *(const uint32_t*)(smem + SM_ALO + o00 + 16);
                aLo[ks][3] = *(const uint32_t*)(smem + SM_ALO + o10 + 16);
            }
        }

        const char* bbase = smem + SM_B + (c & 1) * BBUF;
        #pragma unroll
        for (int o = 0; o < 3; o++) {
            const char* bHi = bbase + o * BT_SZ;
            const char* bLo = bbase + (o + 3) * BT_SZ;
            #pragma unroll
            for (int ks = 0; ks < 4; ks++) {
                const int k0 = ks * 16 + tq * 2;
                uint32_t bf[8][2];
                #pragma unroll
                for (int nt = 0; nt < 8; nt++) {
                    uint32_t ob = (uint32_t)((nt * 8 + g) * AP + k0) * 2;
                    bf[nt][0] = *(const uint32_t*)(bHi + ob);
                    bf[nt][1] = *(const uint32_t*)(bHi + ob + 16);
                }
                #pragma unroll
                for (int nt = 0; nt < 8; nt++) {
                    mma_bf16(d[o][nt], aHi[ks], bf[nt][0], bf[nt][1]);
                    mma_bf16(d[o][nt], aLo[ks], bf[nt][0], bf[nt][1]);
                }
                #pragma unroll
                for (int nt = 0; nt < 8; nt++) {
                    uint32_t ob = (uint32_t)((nt * 8 + g) * AP + k0) * 2;
                    bf[nt][0] = *(const uint32_t*)(bLo + ob);
                    bf[nt][1] = *(const uint32_t*)(bLo + ob + 16);
                }
                #pragma unroll
                for (int nt = 0; nt < 8; nt++)
                    mma_bf16(d[o][nt], aHi[ks], bf[nt][0], bf[nt][1]);
            }
        }
    }
    __syncthreads();

    const size_t r0 = (size_t)(rowBase + wid * 16 + g);
    #pragma unroll
    for (int o = 0; o < 2; o++) {
        __nv_bfloat16 (*dsthi)[H_] = o ? g_khi : g_qhi;
        __nv_bfloat16 (*dstlo)[H_] = o ? g_klo : g_qlo;
        #pragma unroll
        for (int nt = 0; nt < 8; nt++) {
            int col = nt * 8 + tq * 2;
            #pragma unroll
            for (int h = 0; h < 2; h++) {
                float v0 = d[o][nt][h * 2], v1 = d[o][nt][h * 2 + 1];
                __nv_bfloat16 h0 = __float2bfloat16(v0), h1 = __float2bfloat16(v1);
                float l0 = v0 - __bfloat162float(h0), l1 = v1 - __bfloat162float(h1);
                __nv_bfloat162 hp; hp.x = h0; hp.y = h1;
                *(uint32_t*)&dsthi[r0 + h * 8][col] = *(uint32_t*)&hp;
                *(uint32_t*)&dstlo[r0 + h * 8][col] = packbf2(l0, l1);
            }
        }
    }
    {
        __nv_bfloat16 (*sVhi)[VSP] = (__nv_bfloat16(*)[VSP])(smem + SM_B);
        __nv_bfloat16 (*sVlo)[VSP] =
            (__nv_bfloat16(*)[VSP])(smem + SM_B + 64 * VSP * 2);
        int tl0 = wid * 16 + g;
        #pragma unroll
        for (int nt = 0; nt < 8; nt++) {
            #pragma unroll
            for (int j = 0; j < 4; j++) {
                int col = nt * 8 + tq * 2 + (j & 1);
                int tl = tl0 + (j >> 1) * 8;
                float v = d[2][nt][j];
                __nv_bfloat16 hi = __float2bfloat16(v);
                sVhi[col][tl] = hi;
                sVlo[col][tl] = __float2bfloat16(v - __bfloat162float(hi));
            }
        }
        __syncthreads();
        for (int i = tid; i < 64 * 16; i += 256) {
            int h = i >> 4, q8 = i & 15;
            *(uint4*)&g_vthi[h][rowBase + q8 * 8] = *(const uint4*)&sVhi[h][q8 * 8];
            *(uint4*)&g_vtlo[h][rowBase + q8 * 8] = *(const uint4*)&sVlo[h][q8 * 8];
        }
    }
}

// ---------------------------------------------------------------------------
// Flash attention: R14 winner structure (2 warps/SMSP, side loop, cp.async
// double buffer). ONE change: fragment loads via ldmatrix.x4 (validated
// layout; 272 LDS.32 -> ~68 ldmatrix per tile). Data + mma order identical.
// smem: 2 x 36864 + sP 18432 = 92160. grid=(8,2,8), block=256.
// ---------------------------------------------------------------------------
#define APB 72
#define ROWB (APB * 2)          // 144 B; /16 = 9 -> ldmatrix conflict-free
#define TILE_SZ 36864
#define SK_HI 0
#define SK_LO 9216
#define SV_HI 18432
#define SV_LO 27648
#define SP_OFF (2 * TILE_SZ)
#define ATTN_SMEM (SP_OFF + 128 * ROWB)   // 92160

__device__ __forceinline__ void attn_issue_tile(uint32_t sb, int b, int kt, int tid) {
    #pragma unroll
    for (int j = 0; j < 8; j++) {
        int i = tid + j * 256;
        int which = i >> 9, rem = i & 511;
        int r = rem >> 3, q8 = rem & 7;
        const __nv_bfloat16* src;
        if      (which == 0) src = &g_khi[(size_t)b * T_ + kt * 64 + r][q8 * 8];
        else if (which == 1) src = &g_klo[(size_t)b * T_ + kt * 64 + r][q8 * 8];
        else if (which == 2) src = &g_vthi[r][(size_t)b * T_ + kt * 64 + q8 * 8];
        else                 src = &g_vtlo[r][(size_t)b * T_ + kt * 64 + q8 * 8];
        cp_async16(sb + which * 9216 + r * ROWB + q8 * 16, src);
    }
    cp_commit();
}

__global__ void __launch_bounds__(256, 1) attn_kernel() {
    extern __shared__ __align__(16) char sm[];
    const uint32_t sbase = smem_u32(sm);
    const int pair = blockIdx.x;
    const int hf   = blockIdx.y;
    const int b    = blockIdx.z;
    const int tid  = threadIdx.x;
    const int wid  = tid >> 5;
    const int lane = tid & 31;
    const int g    = lane >> 2;
    const int tq   = lane & 3;

    // ldmatrix per-lane addressing:
    // B-operand (K/V, [n][k]): m0/m1 = n-rows 0-7 (k+0 / k+16),
    //                          m2/m3 = n-rows 8-15 -> r0..r3 = b0,b1 of nt pair
    const uint32_t b_row  = ((lane & 16) >> 1) + (lane & 7);   // + ntp*16
    const uint32_t b_kadd = (lane & 8) * 2;
    // A-operand (P, row-major m16): m0=rows0-7 k0 (a0), m1=rows8-15 k0 (a1),
    //                               m2=rows0-7 k16 (a2), m3=rows8-15 k16 (a3)
    const uint32_t p_row  = wid * 16 + (lane & 8) + (lane & 7);
    const uint32_t p_kadd = (lane & 16);

    for (int side = 0; side < 2; side++) {
        const int qt = side ? (NQT128 - 1 - pair) : pair;
        const int row0 = qt * 128 + wid * 16 + g;
        const int row1 = row0 + 8;
        const size_t tok0 = (size_t)b * T_ + row0;

        uint32_t qhi[4][4], qlo[4][4];
        #pragma unroll
        for (int ks = 0; ks < 4; ks++) {
            const int k0 = ks * 16 + tq * 2;
            qhi[ks][0] = *(const uint32_t*)&g_qhi[tok0][k0];
            qhi[ks][1] = *(const uint32_t*)&g_qhi[tok0 + 8][k0];
            qhi[ks][2] = *(const uint32_t*)&g_qhi[tok0][k0 + 8];
            qhi[ks][3] = *(const uint32_t*)&g_qhi[tok0 + 8][k0 + 8];
            qlo[ks][0] = *(const uint32_t*)&g_qlo[tok0][k0];
            qlo[ks][1] = *(const uint32_t*)&g_qlo[tok0 + 8][k0];
            qlo[ks][2] = *(const uint32_t*)&g_qlo[tok0][k0 + 8];
            qlo[ks][3] = *(const uint32_t*)&g_qlo[tok0 + 8][k0 + 8];
        }

        float O[8][4];
        #pragma unroll
        for (int nt = 0; nt < 8; nt++)
            #pragma unroll
            for (int r = 0; r < 4; r++) O[nt][r] = 0.0f;
        float m0 = -1e30f, m1 = -1e30f, l0 = 0.0f, l1 = 0.0f;

        const int kt0 = hf ? (qt + 1)     : 0;
        const int kt1 = hf ? (2 * qt + 2) : (qt + 1);
        const int ntl = kt1 - kt0;

        attn_issue_tile(sbase, b, kt0, tid);

        for (int it = 0; it < ntl; it++) {
            const int kt = kt0 + it;
            const uint32_t bufb = sbase + (it & 1) * TILE_SZ;
            cp_wait0();
            __syncthreads();
            if (it + 1 < ntl)
                attn_issue_tile(sbase + ((it + 1) & 1) * TILE_SZ, b, kt + 1, tid);

            // ---- S = Q K^T, 3-term split (ldmatrix fragments) ----
            float s[8][4];
            #pragma unroll
            for (int nt = 0; nt < 8; nt++)
                #pragma unroll
                for (int r = 0; r < 4; r++) s[nt][r] = 0.0f;
            #pragma unroll
            for (int ks = 0; ks < 4; ks++) {
                const uint32_t kb0 = (uint32_t)ks * 32 + b_kadd;
                #pragma unroll
                for (int ntp = 0; ntp < 4; ntp++) {
                    const uint32_t roff = (ntp * 16 + b_row) * ROWB + kb0;
                    uint32_t h0, h1, h2, h3;
                    ldsm_x4(h0, h1, h2, h3, bufb + SK_HI + roff);
                    mma_bf16(s[ntp * 2],     qhi[ks], h0, h1);
                    mma_bf16(s[ntp * 2],     qlo[ks], h0, h1);
                    mma_bf16(s[ntp * 2 + 1], qhi[ks], h2, h3);
                    mma_bf16(s[ntp * 2 + 1], qlo[ks], h2, h3);
                    uint32_t c0, c1, c2, c3;
                    ldsm_x4(c0, c1, c2, c3, bufb + SK_LO + roff);
                    mma_bf16(s[ntp * 2],     qhi[ks], c0, c1);
                    mma_bf16(s[ntp * 2 + 1], qhi[ks], c2, c3);
                }
            }

            if (kt >= 2 * qt) {
                #pragma unroll
                for (int nt = 0; nt < 8; nt++) {
                    int col = kt * 64 + nt * 8 + tq * 2;
                    if (col > row0)     s[nt][0] = -1e30f;
                    if (col + 1 > row0) s[nt][1] = -1e30f;
                    if (col > row1)     s[nt][2] = -1e30f;
                    if (col + 1 > row1) s[nt][3] = -1e30f;
                }
            }

            // ---- online softmax ----
            float a0 = -1e30f, a1 = -1e30f;
            #pragma unroll
            for (int nt = 0; nt < 8; nt++) {
                a0 = fmaxf(a0, fmaxf(s[nt][0], s[nt][1]));
                a1 = fmaxf(a1, fmaxf(s[nt][2], s[nt][3]));
            }
            a0 = fmaxf(a0, __shfl_xor_sync(0xffffffffu, a0, 1));
            a0 = fmaxf(a0, __shfl_xor_sync(0xffffffffu, a0, 2));
            a1 = fmaxf(a1, __shfl_xor_sync(0xffffffffu, a1, 1));
            a1 = fmaxf(a1, __shfl_xor_sync(0xffffffffu, a1, 2));
            float nm0 = fmaxf(m0, a0), nm1 = fmaxf(m1, a1);
            float sc0 = __expf(m0 - nm0), sc1 = __expf(m1 - nm1);
            float rs0 = 0.0f, rs1 = 0.0f;
            char* prow0 = sm + SP_OFF + (wid * 16 + g) * ROWB;
            #pragma unroll
            for (int nt = 0; nt < 8; nt++) {
                float p00 = __expf(s[nt][0] - nm0), p01 = __expf(s[nt][1] - nm0);
                float p10 = __expf(s[nt][2] - nm1), p11 = __expf(s[nt][3] - nm1);
                __nv_bfloat162 r0p = __floats2bfloat162_rn(p00, p01);
                __nv_bfloat162 r1p = __floats2bfloat162_rn(p10, p11);
                rs0 += __bfloat162float(r0p.x) + __bfloat162float(r0p.y);
                rs1 += __bfloat162float(r1p.x) + __bfloat162float(r1p.y);
                *(uint32_t*)(prow0 + (nt * 8 + tq * 2) * 2) = *(uint32_t*)&r0p;
                *(uint32_t*)(prow0 + 8 * ROWB + (nt * 8 + tq * 2) * 2) = *(uint32_t*)&r1p;
            }
            rs0 += __shfl_xor_sync(0xffffffffu, rs0, 1);
            rs0 += __shfl_xor_sync(0xffffffffu, rs0, 2);
            rs1 += __shfl_xor_sync(0xffffffffu, rs1, 1);
            rs1 += __shfl_xor_sync(0xffffffffu, rs1, 2);
            l0 = l0 * sc0 + rs0; m0 = nm0;
            l1 = l1 * sc1 + rs1; m1 = nm1;
            #pragma unroll
            for (int nt = 0; nt < 8; nt++) {
                O[nt][0] *= sc0; O[nt][1] *= sc0;
                O[nt][2] *= sc1; O[nt][3] *= sc1;
            }
            __syncwarp();   // sP rows are warp-local

            // ---- O += P @ V (ldmatrix fragments) ----
            #pragma unroll
            for (int ks = 0; ks < 4; ks++) {
                uint32_t pa[4];
                ldsm_x4(pa[0], pa[1], pa[2], pa[3],
                        sbase + SP_OFF + p_row * ROWB + (uint32_t)ks * 32 + p_kadd);
                const uint32_t kb0 = (uint32_t)ks * 32 + b_kadd;
                #pragma unroll
                for (int ntp = 0; ntp < 4; ntp++) {
                    const uint32_t roff = (ntp * 16 + b_row) * ROWB + kb0;
                    uint32_t h0, h1, h2, h3;
                    ldsm_x4(h0, h1, h2, h3, bufb + SV_HI + roff);
                    mma_bf16(O[ntp * 2],     pa, h0, h1);
                    mma_bf16(O[ntp * 2 + 1], pa, h2, h3);
                    uint32_t c0, c1, c2, c3;
                    ldsm_x4(c0, c1, c2, c3, bufb + SV_LO + roff);
                    mma_bf16(O[ntp * 2],     pa, c0, c1);
                    mma_bf16(O[ntp * 2 + 1], pa, c2, c3);
                }
            }
        }
        __syncthreads();

        if (tq == 0) {
            g_pm[hf][b][row0] = m0; g_pl[hf][b][row0] = l0;
            g_pm[hf][b][row1] = m1; g_pl[hf][b][row1] = l1;
        }
        #pragma unroll
        for (int nt = 0; nt < 8; nt++) {
            int col = nt * 8 + tq * 2;
            *(float2*)&g_po[hf][b][row0][col] = make_float2(O[nt][0], O[nt][1]);
            *(float2*)&g_po[hf][b][row1][col] = make_float2(O[nt][2], O[nt][3]);
        }
    }
}

// ---------------------------------------------------------------------------
// Merge split-K halves.
// ---------------------------------------------------------------------------
__global__ void merge_kernel(float* __restrict__ out) {
    int idx = blockIdx.x * 256 + threadIdx.x;
    int row = idx >> 4;
    int c4  = idx & 15;
    int b = row >> 11;
    int t = row & 2047;

    float m0 = g_pm[0][b][t], m1 = g_pm[1][b][t];
    float l0 = g_pl[0][b][t], l1 = g_pl[1][b][t];
    float M  = fmaxf(m0, m1);
    float e0 = __expf(m0 - M), e1 = __expf(m1 - M);
    float inv = 1.0f / (l0 * e0 + l1 * e1);

    float4 a0 = *(const float4*)&g_po[0][b][t][c4 * 4];
    float4 a1 = *(const float4*)&g_po[1][b][t][c4 * 4];
    float4 o;
    o.x = (a0.x * e0 + a1.x * e1) * inv;
    o.y = (a0.y * e0 + a1.y * e1) * inv;
    o.z = (a0.z * e0 + a1.z * e1) * inv;
    o.w = (a0.w * e0 + a1.w * e1) * inv;
    *(float4*)&out[(size_t)row * H_ + c4 * 4] = o;
}

// ---------------------------------------------------------------------------
// Harness entry. Inputs: x [B,T,C], Wq, Wk, Wv [C,H]. Output: [B,T,H] f32.
// ---------------------------------------------------------------------------
extern "C" void kernel_launch(void* const* d_in, const int* in_sizes, int n_in,
                              void* d_out, int out_size) {
    const float* x  = (const float*)d_in[0];
    const float* Wq = (const float*)d_in[1];
    const float* Wk = (const float*)d_in[2];
    const float* Wv = (const float*)d_in[3];
    float* out = (float*)d_out;
    (void)in_sizes; (void)n_in; (void)out_size;

    cudaFuncSetAttribute(proj_kernel, cudaFuncAttributeMaxDynamicSharedMemorySize,
                         PROJ_SMEM);
    cudaFuncSetAttribute(attn_kernel, cudaFuncAttributeMaxDynamicSharedMemorySize,
                         ATTN_SMEM);

    prep_w_kernel<<<384, 256>>>(Wq, Wk, Wv);
    proj_kernel<<<128, 256, PROJ_SMEM>>>(x);
    attn_kernel<<<dim3(NPAIR, 2, B_), 256, ATTN_SMEM>>>();
    merge_kernel<<<(B_ * T_ * (H_ / 4)) / 256, 256>>>(out);
}

// round 17
// speedup vs baseline: 1.4318x; 1.0227x over previous
#include <cuda_runtime.h>
#include <cuda_bf16.h>
#include <cstdint>
#include <math.h>

#define B_ 8
#define T_ 2048
#define C_ 512
#define H_ 64
#define NQT128 (T_ / 128)     // 16 q-tiles of 128 rows
#define NPAIR (NQT128 / 2)    // 8 balanced pairs

// ---- device scratch (no allocations allowed) ----
__device__ __align__(16) __nv_bfloat16 g_whi[3][H_][C_];
__device__ __align__(16) __nv_bfloat16 g_wlo[3][H_][C_];
__device__ __align__(16) __nv_bfloat16 g_qhi[B_ * T_][H_];
__device__ __align__(16) __nv_bfloat16 g_qlo[B_ * T_][H_];
__device__ __align__(16) __nv_bfloat16 g_khi[B_ * T_][H_];
__device__ __align__(16) __nv_bfloat16 g_klo[B_ * T_][H_];
__device__ __align__(16) __nv_bfloat16 g_vthi[H_][B_ * T_];
__device__ __align__(16) __nv_bfloat16 g_vtlo[H_][B_ * T_];
__device__ __align__(16) float g_pm[2][B_][T_];
__device__ __align__(16) float g_pl[2][B_][T_];
__device__ __align__(16) float g_po[2][B_][T_][H_];

// ---- helpers ----
__device__ __forceinline__ void mma_bf16(float* d, const uint32_t* a, uint32_t b0,
                                         uint32_t b1) {
    asm volatile(
        "mma.sync.aligned.m16n8k16.row.col.f32.bf16.bf16.f32 "
        "{%0,%1,%2,%3}, {%4,%5,%6,%7}, {%8,%9}, {%0,%1,%2,%3};"
        : "+f"(d[0]), "+f"(d[1]), "+f"(d[2]), "+f"(d[3])
        : "r"(a[0]), "r"(a[1]), "r"(a[2]), "r"(a[3]), "r"(b0), "r"(b1));
}
__device__ __forceinline__ void ldsm_x4(uint32_t& r0, uint32_t& r1, uint32_t& r2,
                                        uint32_t& r3, uint32_t addr) {
    asm volatile("ldmatrix.sync.aligned.m8n8.x4.shared.b16 {%0,%1,%2,%3}, [%4];"
                 : "=r"(r0), "=r"(r1), "=r"(r2), "=r"(r3) : "r"(addr));
}
__device__ __forceinline__ uint32_t packbf2(float a, float b) {
    __nv_bfloat162 t = __floats2bfloat162_rn(a, b);
    return *(uint32_t*)&t;
}
__device__ __forceinline__ uint32_t smem_u32(const void* p) {
    uint32_t a;
    asm("{ .reg .u64 t; cvta.to.shared.u64 t, %1; cvt.u32.u64 %0, t; }" : "=r"(a) : "l"(p));
    return a;
}
__device__ __forceinline__ void cp_async16(uint32_t dst, const void* src) {
    asm volatile("cp.async.cg.shared.global [%0], [%1], 16;" :: "r"(dst), "l"(src));
}
__device__ __forceinline__ void cp_commit() {
    asm volatile("cp.async.commit_group;" ::: "memory");
}
__device__ __forceinline__ void cp_wait0() {
    asm volatile("cp.async.wait_group 0;" ::: "memory");
}
__device__ __forceinline__ void cp_wait1() {
    asm volatile("cp.async.wait_group 1;" ::: "memory");
}

// ---------------------------------------------------------------------------
// prep_w v2 (R14): coalesced reads.
// ---------------------------------------------------------------------------
__global__ void prep_w_kernel(const float* __restrict__ Wq,
                              const float* __restrict__ Wk,
                              const float* __restrict__ Wv) {
    int idx = blockIdx.x * 256 + threadIdx.x;
    int o = idx >> 15;
    int k = (idx >> 6) & 511;
    int n = idx & 63;
    const float* W = (o == 0) ? Wq : ((o == 1) ? Wk : Wv);
    float v = W[(size_t)k * H_ + n];
    __nv_bfloat16 hi = __float2bfloat16(v);
    __nv_bfloat16 lo = __float2bfloat16(v - __bfloat162float(hi));
    g_whi[o][n][k] = hi;
    g_wlo[o][n][k] = lo;
}

// ---------------------------------------------------------------------------
// Projection v8: chunk pipeline (R14) + ldmatrix fragment loads (the
// attn-validated A/B patterns). Per-accumulator mma order preserved.
// grid = 128, block = 256 (8 warps), dynamic smem = 147456 B
// ---------------------------------------------------------------------------
#define AP 72
#define APROWB (AP * 2)                // 144 B row stride (ldmatrix-clean)
#define SM_AHI 0
#define SM_ALO (128 * AP * 2)          // 18432
#define SM_B   (2 * 128 * AP * 2)      // 36864
#define BT_SZ  (64 * AP * 2)           // 9216
#define BBUF   (6 * BT_SZ)             // 55296
#define PROJ_SMEM (SM_B + 2 * BBUF)    // 147456
#define VSP 136

__device__ __forceinline__ void proj_issue_b(uint32_t sbB, int c, int tid) {
    #pragma unroll
    for (int j = 0; j < 12; j++) {
        int i = tid + j * 256;
        int t = i >> 9, rem = i & 511;
        int n = rem >> 3, q8 = rem & 7;
        int o = (t >= 3) ? (t - 3) : t;
        const __nv_bfloat16* src = (t >= 3) ? &g_wlo[o][n][c * 64 + q8 * 8]
                                            : &g_whi[o][n][c * 64 + q8 * 8];
        cp_async16(sbB + (uint32_t)(t * BT_SZ + (n * AP + q8 * 8) * 2), src);
    }
    cp_commit();
}
__device__ __forceinline__ void proj_load_x(const float* __restrict__ x,
                                            int rowBase, int c, int tid, float4* xv) {
    #pragma unroll
    for (int j = 0; j < 8; j++) {
        int i = tid + j * 256;
        int r = i >> 4, q4 = i & 15;
        xv[j] = *(const float4*)&x[(size_t)(rowBase + r) * C_ + c * 64 + q4 * 4];
    }
}

__global__ void __launch_bounds__(256, 1) proj_kernel(const float* __restrict__ x) {
    extern __shared__ __align__(16) char smem[];
    const uint32_t sbase = smem_u32(smem);
    const int tid = threadIdx.x;
    const int wid = tid >> 5;
    const int lane = tid & 31;
    const int g = lane >> 2;
    const int tq = lane & 3;
    const int rowBase = blockIdx.x * 128;

    // ldmatrix lane addressing (validated in attn):
    const uint32_t a_row  = wid * 16 + (lane & 8) + (lane & 7);   // A row-major
    const uint32_t a_kadd = (lane & 16);
    const uint32_t b_row  = ((lane & 16) >> 1) + (lane & 7);      // B [n][k]
    const uint32_t b_kadd = (lane & 8) * 2;

    float d[3][8][4];
    #pragma unroll
    for (int o = 0; o < 3; o++)
        #pragma unroll
        for (int nt = 0; nt < 8; nt++)
            #pragma unroll
            for (int r = 0; r < 4; r++) d[o][nt][r] = 0.0f;

    float4 xv[8];
    proj_issue_b(sbase + SM_B, 0, tid);
    proj_load_x(x, rowBase, 0, tid, xv);

    for (int c = 0; c < 8; c++) {
        __syncthreads();   // A-buffer WAR vs mma(c-1)
        #pragma unroll
        for (int j = 0; j < 8; j++) {
            int i = tid + j * 256;
            int r = i >> 4, q4 = i & 15;
            float4 v = xv[j];
            __nv_bfloat16 h0 = __float2bfloat16(v.x), h1 = __float2bfloat16(v.y);
            __nv_bfloat16 h2 = __float2bfloat16(v.z), h3 = __float2bfloat16(v.w);
            float l0 = v.x - __bfloat162float(h0), l1 = v.y - __bfloat162float(h1);
            float l2 = v.z - __bfloat162float(h2), l3 = v.w - __bfloat162float(h3);
            uint32_t off = (uint32_t)(r * AP + q4 * 4) * 2;
            __nv_bfloat162 hA; hA.x = h0; hA.y = h1;
            __nv_bfloat162 hB; hB.x = h2; hB.y = h3;
            *(uint2*)(smem + SM_AHI + off) = make_uint2(*(uint32_t*)&hA, *(uint32_t*)&hB);
            *(uint2*)(smem + SM_ALO + off) = make_uint2(packbf2(l0, l1), packbf2(l2, l3));
        }
        if (c < 7) {
            proj_load_x(x, rowBase, c + 1, tid, xv);
            proj_issue_b(sbase + SM_B + ((c + 1) & 1) * BBUF, c + 1, tid);
            cp_wait1();
        } else {
            cp_wait0();
        }
        __syncthreads();

        // ---- A fragments via ldmatrix ----
        uint32_t aHi[4][4], aLo[4][4];
        #pragma unroll
        for (int ks = 0; ks < 4; ks++) {
            uint32_t off = a_row * APROWB + (uint32_t)ks * 32 + a_kadd;
            ldsm_x4(aHi[ks][0], aHi[ks][1], aHi[ks][2], aHi[ks][3],
                    sbase + SM_AHI + off);
            ldsm_x4(aLo[ks][0], aLo[ks][1], aLo[ks][2], aLo[ks][3],
                    sbase + SM_ALO + off);
        }

        const uint32_t bb = sbase + SM_B + (uint32_t)((c & 1) * BBUF);
        #pragma unroll
        for (int o = 0; o < 3; o++) {
            const uint32_t bHi = bb + o * BT_SZ;
            const uint32_t bLo = bb + (o + 3) * BT_SZ;
            #pragma unroll
            for (int ks = 0; ks < 4; ks++) {
                const uint32_t kb0 = (uint32_t)ks * 32 + b_kadd;
                // hi pass: per accumulator hi*hi then lo*hi (order preserved)
                #pragma unroll
                for (int ntp = 0; ntp < 4; ntp++) {
                    const uint32_t roff = (ntp * 16 + b_row) * APROWB + kb0;
                    uint32_t h0, h1, h2, h3;
                    ldsm_x4(h0, h1, h2, h3, bHi + roff);
                    mma_bf16(d[o][ntp * 2],     aHi[ks], h0, h1);
                    mma_bf16(d[o][ntp * 2],     aLo[ks], h0, h1);
                    mma_bf16(d[o][ntp * 2 + 1], aHi[ks], h2, h3);
                    mma_bf16(d[o][ntp * 2 + 1], aLo[ks], h2, h3);
                }
                // lo pass: hi*lo
                #pragma unroll
                for (int ntp = 0; ntp < 4; ntp++) {
                    const uint32_t roff = (ntp * 16 + b_row) * APROWB + kb0;
                    uint32_t c0, c1, c2, c3;
                    ldsm_x4(c0, c1, c2, c3, bLo + roff);
                    mma_bf16(d[o][ntp * 2],     aHi[ks], c0, c1);
                    mma_bf16(d[o][ntp * 2 + 1], aHi[ks], c2, c3);
                }
            }
        }
    }
    __syncthreads();

    const size_t r0 = (size_t)(rowBase + wid * 16 + g);
    #pragma unroll
    for (int o = 0; o < 2; o++) {
        __nv_bfloat16 (*dsthi)[H_] = o ? g_khi : g_qhi;
        __nv_bfloat16 (*dstlo)[H_] = o ? g_klo : g_qlo;
        #pragma unroll
        for (int nt = 0; nt < 8; nt++) {
            int col = nt * 8 + tq * 2;
            #pragma unroll
            for (int h = 0; h < 2; h++) {
                float v0 = d[o][nt][h * 2], v1 = d[o][nt][h * 2 + 1];
                __nv_bfloat16 h0 = __float2bfloat16(v0), h1 = __float2bfloat16(v1);
                float l0 = v0 - __bfloat162float(h0), l1 = v1 - __bfloat162float(h1);
                __nv_bfloat162 hp; hp.x = h0; hp.y = h1;
                *(uint32_t*)&dsthi[r0 + h * 8][col] = *(uint32_t*)&hp;
                *(uint32_t*)&dstlo[r0 + h * 8][col] = packbf2(l0, l1);
            }
        }
    }
    {
        __nv_bfloat16 (*sVhi)[VSP] = (__nv_bfloat16(*)[VSP])(smem + SM_B);
        __nv_bfloat16 (*sVlo)[VSP] =
            (__nv_bfloat16(*)[VSP])(smem + SM_B + 64 * VSP * 2);
        int tl0 = wid * 16 + g;
        #pragma unroll
        for (int nt = 0; nt < 8; nt++) {
            #pragma unroll
            for (int j = 0; j < 4; j++) {
                int col = nt * 8 + tq * 2 + (j & 1);
                int tl = tl0 + (j >> 1) * 8;
                float v = d[2][nt][j];
                __nv_bfloat16 hi = __float2bfloat16(v);
                sVhi[col][tl] = hi;
                sVlo[col][tl] = __float2bfloat16(v - __bfloat162float(hi));
            }
        }
        __syncthreads();
        for (int i = tid; i < 64 * 16; i += 256) {
            int h = i >> 4, q8 = i & 15;
            *(uint4*)&g_vthi[h][rowBase + q8 * 8] = *(const uint4*)&sVhi[h][q8 * 8];
            *(uint4*)&g_vtlo[h][rowBase + q8 * 8] = *(const uint4*)&sVlo[h][q8 * 8];
        }
    }
}

// ---------------------------------------------------------------------------
// Flash attention: R16 winner, byte-for-byte.
// ---------------------------------------------------------------------------
#define APB 72
#define ROWB (APB * 2)
#define TILE_SZ 36864
#define SK_HI 0
#define SK_LO 9216
#define SV_HI 18432
#define SV_LO 27648
#define SP_OFF (2 * TILE_SZ)
#define ATTN_SMEM (SP_OFF + 128 * ROWB)   // 92160

__device__ __forceinline__ void attn_issue_tile(uint32_t sb, int b, int kt, int tid) {
    #pragma unroll
    for (int j = 0; j < 8; j++) {
        int i = tid + j * 256;
        int which = i >> 9, rem = i & 511;
        int r = rem >> 3, q8 = rem & 7;
        const __nv_bfloat16* src;
        if      (which == 0) src = &g_khi[(size_t)b * T_ + kt * 64 + r][q8 * 8];
        else if (which == 1) src = &g_klo[(size_t)b * T_ + kt * 64 + r][q8 * 8];
        else if (which == 2) src = &g_vthi[r][(size_t)b * T_ + kt * 64 + q8 * 8];
        else                 src = &g_vtlo[r][(size_t)b * T_ + kt * 64 + q8 * 8];
        cp_async16(sb + which * 9216 + r * ROWB + q8 * 16, src);
    }
    cp_commit();
}

__global__ void __launch_bounds__(256, 1) attn_kernel() {
    extern __shared__ __align__(16) char sm[];
    const uint32_t sbase = smem_u32(sm);
    const int pair = blockIdx.x;
    const int hf   = blockIdx.y;
    const int b    = blockIdx.z;
    const int tid  = threadIdx.x;
    const int wid  = tid >> 5;
    const int lane = tid & 31;
    const int g    = lane >> 2;
    const int tq   = lane & 3;

    const uint32_t b_row  = ((lane & 16) >> 1) + (lane & 7);
    const uint32_t b_kadd = (lane & 8) * 2;
    const uint32_t p_row  = wid * 16 + (lane & 8) + (lane & 7);
    const uint32_t p_kadd = (lane & 16);

    for (int side = 0; side < 2; side++) {
        const int qt = side ? (NQT128 - 1 - pair) : pair;
        const int row0 = qt * 128 + wid * 16 + g;
        const int row1 = row0 + 8;
        const size_t tok0 = (size_t)b * T_ + row0;

        uint32_t qhi[4][4], qlo[4][4];
        #pragma unroll
        for (int ks = 0; ks < 4; ks++) {
            const int k0 = ks * 16 + tq * 2;
            qhi[ks][0] = *(const uint32_t*)&g_qhi[tok0][k0];
            qhi[ks][1] = *(const uint32_t*)&g_qhi[tok0 + 8][k0];
            qhi[ks][2] = *(const uint32_t*)&g_qhi[tok0][k0 + 8];
            qhi[ks][3] = *(const uint32_t*)&g_qhi[tok0 + 8][k0 + 8];
            qlo[ks][0] = *(const uint32_t*)&g_qlo[tok0][k0];
            qlo[ks][1] = *(const uint32_t*)&g_qlo[tok0 + 8][k0];
            qlo[ks][2] = *(const uint32_t*)&g_qlo[tok0][k0 + 8];
            qlo[ks][3] = *(const uint32_t*)&g_qlo[tok0 + 8][k0 + 8];
        }

        float O[8][4];
        #pragma unroll
        for (int nt = 0; nt < 8; nt++)
            #pragma unroll
            for (int r = 0; r < 4; r++) O[nt][r] = 0.0f;
        float m0 = -1e30f, m1 = -1e30f, l0 = 0.0f, l1 = 0.0f;

        const int kt0 = hf ? (qt + 1)     : 0;
        const int kt1 = hf ? (2 * qt + 2) : (qt + 1);
        const int ntl = kt1 - kt0;

        attn_issue_tile(sbase, b, kt0, tid);

        for (int it = 0; it < ntl; it++) {
            const int kt = kt0 + it;
            const uint32_t bufb = sbase + (it & 1) * TILE_SZ;
            cp_wait0();
            __syncthreads();
            if (it + 1 < ntl)
                attn_issue_tile(sbase + ((it + 1) & 1) * TILE_SZ, b, kt + 1, tid);

            float s[8][4];
            #pragma unroll
            for (int nt = 0; nt < 8; nt++)
                #pragma unroll
                for (int r = 0; r < 4; r++) s[nt][r] = 0.0f;
            #pragma unroll
            for (int ks = 0; ks < 4; ks++) {
                const uint32_t kb0 = (uint32_t)ks * 32 + b_kadd;
                #pragma unroll
                for (int ntp = 0; ntp < 4; ntp++) {
                    const uint32_t roff = (ntp * 16 + b_row) * ROWB + kb0;
                    uint32_t h0, h1, h2, h3;
                    ldsm_x4(h0, h1, h2, h3, bufb + SK_HI + roff);
                    mma_bf16(s[ntp * 2],     qhi[ks], h0, h1);
                    mma_bf16(s[ntp * 2],     qlo[ks], h0, h1);
                    mma_bf16(s[ntp * 2 + 1], qhi[ks], h2, h3);
                    mma_bf16(s[ntp * 2 + 1], qlo[ks], h2, h3);
                    uint32_t c0, c1, c2, c3;
                    ldsm_x4(c0, c1, c2, c3, bufb + SK_LO + roff);
                    mma_bf16(s[ntp * 2],     qhi[ks], c0, c1);
                    mma_bf16(s[ntp * 2 + 1], qhi[ks], c2, c3);
                }
            }

            if (kt >= 2 * qt) {
                #pragma unroll
                for (int nt = 0; nt < 8; nt++) {
                    int col = kt * 64 + nt * 8 + tq * 2;
                    if (col > row0)     s[nt][0] = -1e30f;
                    if (col + 1 > row0) s[nt][1] = -1e30f;
                    if (col > row1)     s[nt][2] = -1e30f;
                    if (col + 1 > row1) s[nt][3] = -1e30f;
                }
            }

            float a0 = -1e30f, a1 = -1e30f;
            #pragma unroll
            for (int nt = 0; nt < 8; nt++) {
                a0 = fmaxf(a0, fmaxf(s[nt][0], s[nt][1]));
                a1 = fmaxf(a1, fmaxf(s[nt][2], s[nt][3]));
            }
            a0 = fmaxf(a0, __shfl_xor_sync(0xffffffffu, a0, 1));
            a0 = fmaxf(a0, __shfl_xor_sync(0xffffffffu, a0, 2));
            a1 = fmaxf(a1, __shfl_xor_sync(0xffffffffu, a1, 1));
            a1 = fmaxf(a1, __shfl_xor_sync(0xffffffffu, a1, 2));
            float nm0 = fmaxf(m0, a0), nm1 = fmaxf(m1, a1);
            float sc0 = __expf(m0 - nm0), sc1 = __expf(m1 - nm1);
            float rs0 = 0.0f, rs1 = 0.0f;
            char* prow0 = sm + SP_OFF + (wid * 16 + g) * ROWB;
            #pragma unroll
            for (int nt = 0; nt < 8; nt++) {
                float p00 = __expf(s[nt][0] - nm0), p01 = __expf(s[nt][1] - nm0);
                float p10 = __expf(s[nt][2] - nm1), p11 = __expf(s[nt][3] - nm1);
                __nv_bfloat162 r0p = __floats2bfloat162_rn(p00, p01);
                __nv_bfloat162 r1p = __floats2bfloat162_rn(p10, p11);
                rs0 += __bfloat162float(r0p.x) + __bfloat162float(r0p.y);
                rs1 += __bfloat162float(r1p.x) + __bfloat162float(r1p.y);
                *(uint32_t*)(prow0 + (nt * 8 + tq * 2) * 2) = *(uint32_t*)&r0p;
                *(uint32_t*)(prow0 + 8 * ROWB + (nt * 8 + tq * 2) * 2) = *(uint32_t*)&r1p;
            }
            rs0 += __shfl_xor_sync(0xffffffffu, rs0, 1);
            rs0 += __shfl_xor_sync(0xffffffffu, rs0, 2);
            rs1 += __shfl_xor_sync(0xffffffffu, rs1, 1);
            rs1 += __shfl_xor_sync(0xffffffffu, rs1, 2);
            l0 = l0 * sc0 + rs0; m0 = nm0;
            l1 = l1 * sc1 + rs1; m1 = nm1;
            #pragma unroll
            for (int nt = 0; nt < 8; nt++) {
                O[nt][0] *= sc0; O[nt][1] *= sc0;
                O[nt][2] *= sc1; O[nt][3] *= sc1;
            }
            __syncwarp();

            #pragma unroll
            for (int ks = 0; ks < 4; ks++) {
                uint32_t pa[4];
                ldsm_x4(pa[0], pa[1], pa[2], pa[3],
                        sbase + SP_OFF + p_row * ROWB + (uint32_t)ks * 32 + p_kadd);
                const uint32_t kb0 = (uint32_t)ks * 32 + b_kadd;
                #pragma unroll
                for (int ntp = 0; ntp < 4; ntp++) {
                    const uint32_t roff = (ntp * 16 + b_row) * ROWB + kb0;
                    uint32_t h0, h1, h2, h3;
                    ldsm_x4(h0, h1, h2, h3, bufb + SV_HI + roff);
                    mma_bf16(O[ntp * 2],     pa, h0, h1);
                    mma_bf16(O[ntp * 2 + 1], pa, h2, h3);
                    uint32_t c0, c1, c2, c3;
                    ldsm_x4(c0, c1, c2, c3, bufb + SV_LO + roff);
                    mma_bf16(O[ntp * 2],     pa, c0, c1);
                    mma_bf16(O[ntp * 2 + 1], pa, c2, c3);
                }
            }
        }
        __syncthreads();

        if (tq == 0) {
            g_pm[hf][b][row0] = m0; g_pl[hf][b][row0] = l0;
            g_pm[hf][b][row1] = m1; g_pl[hf][b][row1] = l1;
        }
        #pragma unroll
        for (int nt = 0; nt < 8; nt++) {
            int col = nt * 8 + tq * 2;
            *(float2*)&g_po[hf][b][row0][col] = make_float2(O[nt][0], O[nt][1]);
            *(float2*)&g_po[hf][b][row1][col] = make_float2(O[nt][2], O[nt][3]);
        }
    }
}

// ---------------------------------------------------------------------------
// Merge v2: 2 H-chunks per thread -> 4 independent LDG.128 in flight
// (memory-latency bound at MLP 2 before; now MLP 4+). grid = 512.
// ---------------------------------------------------------------------------
__global__ void merge_kernel(float* __restrict__ out) {
    int idx = blockIdx.x * 256 + threadIdx.x;   // 0 .. 16384*8-1
    int row = idx >> 3;
    int c4  = idx & 7;                           // chunks c4 and c4+8
    int b = row >> 11;
    int t = row & 2047;

    float m0 = g_pm[0][b][t], m1 = g_pm[1][b][t];
    float l0 = g_pl[0][b][t], l1 = g_pl[1][b][t];

    float4 a0x = *(const float4*)&g_po[0][b][t][c4 * 4];
    float4 a1x = *(const float4*)&g_po[1][b][t][c4 * 4];
    float4 a0y = *(const float4*)&g_po[0][b][t][(c4 + 8) * 4];
    float4 a1y = *(const float4*)&g_po[1][b][t][(c4 + 8) * 4];

    float M  = fmaxf(m0, m1);
    float e0 = __expf(m0 - M), e1 = __expf(m1 - M);
    float inv = 1.0f / (l0 * e0 + l1 * e1);

    float4 ox, oy;
    ox.x = (a0x.x * e0 + a1x.x * e1) * inv;
    ox.y = (a0x.y * e0 + a1x.y * e1) * inv;
    ox.z = (a0x.z * e0 + a1x.z * e1) * inv;
    ox.w = (a0x.w * e0 + a1x.w * e1) * inv;
    oy.x = (a0y.x * e0 + a1y.x * e1) * inv;
    oy.y = (a0y.y * e0 + a1y.y * e1) * inv;
    oy.z = (a0y.z * e0 + a1y.z * e1) * inv;
    oy.w = (a0y.w * e0 + a1y.w * e1) * inv;
    *(float4*)&out[(size_t)row * H_ + c4 * 4]       = ox;
    *(float4*)&out[(size_t)row * H_ + (c4 + 8) * 4] = oy;
}

// ---------------------------------------------------------------------------
// Harness entry. Inputs: x [B,T,C], Wq, Wk, Wv [C,H]. Output: [B,T,H] f32.
// ---------------------------------------------------------------------------
extern "C" void kernel_launch(void* const* d_in, const int* in_sizes, int n_in,
                              void* d_out, int out_size) {
    const float* x  = (const float*)d_in[0];
    const float* Wq = (const float*)d_in[1];
    const float* Wk = (const float*)d_in[2];
    const float* Wv = (const float*)d_in[3];
    float* out = (float*)d_out;
    (void)in_sizes; (void)n_in; (void)out_size;

    cudaFuncSetAttribute(proj_kernel, cudaFuncAttributeMaxDynamicSharedMemorySize,
                         PROJ_SMEM);
    cudaFuncSetAttribute(attn_kernel, cudaFuncAttributeMaxDynamicSharedMemorySize,
                         ATTN_SMEM);

    prep_w_kernel<<<384, 256>>>(Wq, Wk, Wv);
    proj_kernel<<<128, 256, PROJ_SMEM>>>(x);
    attn_kernel<<<dim3(NPAIR, 2, B_), 256, ATTN_SMEM>>>();
    merge_kernel<<<(B_ * T_ * (H_ / 8)) / 256, 256>>>(out);
}